// round 1
// baseline (speedup 1.0000x reference)
#include <cuda_runtime.h>
#include <stdint.h>

#define SDIM 64
#define CCH 32
#define KEYSPACE (SDIM*SDIM*SDIM*SDIM)   // 16,777,216
#define NWORDS (KEYSPACE/32)             // 524,288
#define SCAN_BLOCKS 512
#define SCAN_TPB 1024                    // 512*1024 = 524,288 words
#define NMAX (1<<20)                     // >= 1,000,000

__device__ unsigned int g_bitmap[NWORDS];
__device__ unsigned int g_wordpfx[NWORDS];
__device__ unsigned int g_keys[NMAX];
__device__ unsigned int g_blocksums[SCAN_BLOCKS];

// ---------------------------------------------------------------- zero out
__global__ void zero_out_kernel(float4* p, int n4) {
    int i = blockIdx.x * blockDim.x + threadIdx.x;
    if (i < n4) p[i] = make_float4(0.f, 0.f, 0.f, 0.f);
}

__global__ void zero_bitmap_kernel() {
    int i = blockIdx.x * blockDim.x + threadIdx.x;
    if (i < NWORDS / 4) {
        ((uint4*)g_bitmap)[i] = make_uint4(0u, 0u, 0u, 0u);
    }
}

// ------------------------------------------------------- mark presence bits
__global__ void mark_kernel(const int4* __restrict__ coords, int n) {
    int i = blockIdx.x * blockDim.x + threadIdx.x;
    if (i >= n) return;
    int4 c = coords[i];
    unsigned int k = ((unsigned)((c.x * SDIM + c.y) * SDIM + c.z)) * SDIM + (unsigned)c.w;
    g_keys[i] = k;
    atomicOr(&g_bitmap[k >> 5], 1u << (k & 31));
}

// --------------------------------------------- scan pass 1: per-block sums
__global__ void scan_p1() {
    int gid = blockIdx.x * SCAN_TPB + threadIdx.x;
    int v = __popc(g_bitmap[gid]);
    __shared__ int warpsum[32];
    #pragma unroll
    for (int o = 16; o; o >>= 1) v += __shfl_down_sync(0xFFFFFFFFu, v, o);
    if ((threadIdx.x & 31) == 0) warpsum[threadIdx.x >> 5] = v;
    __syncthreads();
    if (threadIdx.x < 32) {
        int s = warpsum[threadIdx.x];
        #pragma unroll
        for (int o = 16; o; o >>= 1) s += __shfl_down_sync(0xFFFFFFFFu, s, o);
        if (threadIdx.x == 0) g_blocksums[blockIdx.x] = (unsigned)s;
    }
}

// ------------------------------------- scan pass 2: scan the 512 block sums
__global__ void scan_p2() {
    __shared__ unsigned int sh[SCAN_BLOCKS];
    unsigned int v = g_blocksums[threadIdx.x];
    sh[threadIdx.x] = v;
    __syncthreads();
    for (int o = 1; o < SCAN_BLOCKS; o <<= 1) {
        unsigned int t = (threadIdx.x >= (unsigned)o) ? sh[threadIdx.x - o] : 0u;
        __syncthreads();
        sh[threadIdx.x] += t;
        __syncthreads();
    }
    g_blocksums[threadIdx.x] = sh[threadIdx.x] - v;   // exclusive
}

// -------------------------- scan pass 3: per-word exclusive prefix popcount
__global__ void scan_p3() {
    __shared__ unsigned int sh[SCAN_TPB];
    int gid = blockIdx.x * SCAN_TPB + threadIdx.x;
    unsigned int v = __popc(g_bitmap[gid]);
    sh[threadIdx.x] = v;
    __syncthreads();
    for (int o = 1; o < SCAN_TPB; o <<= 1) {
        unsigned int t = (threadIdx.x >= (unsigned)o) ? sh[threadIdx.x - o] : 0u;
        __syncthreads();
        sh[threadIdx.x] += t;
        __syncthreads();
    }
    g_wordpfx[gid] = g_blocksums[blockIdx.x] + sh[threadIdx.x] - v;
}

// -------------------------------------------------------- scatter features
// one thread per (point, 4-channel group): 8 threads/point, coalesced float4
__global__ void scatter_kernel(const float4* __restrict__ feats,
                               float* __restrict__ out, int n) {
    int t = blockIdx.x * blockDim.x + threadIdx.x;
    if (t >= n * 8) return;
    int i = t >> 3;
    int g = t & 7;
    unsigned int k = g_keys[i];
    unsigned int w = k >> 5;
    unsigned int b = k & 31;
    unsigned int rank = g_wordpfx[w] + __popc(g_bitmap[w] & ((1u << b) - 1u));
    float4 f = feats[i * 8 + g];
    float* dst = out + (size_t)rank * CCH + g * 4;
    atomicAdd(dst + 0, f.x);
    atomicAdd(dst + 1, f.y);
    atomicAdd(dst + 2, f.z);
    atomicAdd(dst + 3, f.w);
}

extern "C" void kernel_launch(void* const* d_in, const int* in_sizes, int n_in,
                              void* d_out, int out_size) {
    const int4*   coords = (const int4*)d_in[0];
    const float4* feats  = (const float4*)d_in[1];
    float*        out    = (float*)d_out;
    int n = in_sizes[0] / 4;   // N points

    // 1. zero output (padding rows must be 0; atomicAdd needs zeroed base)
    int n4 = out_size / 4;
    zero_out_kernel<<<(n4 + 255) / 256, 256>>>((float4*)d_out, n4);

    // 2. zero presence bitmap
    zero_bitmap_kernel<<<(NWORDS / 4 + 255) / 256, 256>>>();

    // 3. mark keys
    mark_kernel<<<(n + 255) / 256, 256>>>(coords, n);

    // 4-6. exclusive prefix popcount over bitmap words
    scan_p1<<<SCAN_BLOCKS, SCAN_TPB>>>();
    scan_p2<<<1, SCAN_BLOCKS>>>();
    scan_p3<<<SCAN_BLOCKS, SCAN_TPB>>>();

    // 7. scatter-add features into ranked rows
    int tthreads = n * 8;
    scatter_kernel<<<(tthreads + 255) / 256, 256>>>(feats, out, n);
}

// round 3
// speedup vs baseline: 1.3373x; 1.3373x over previous
#include <cuda_runtime.h>
#include <stdint.h>

#define SDIM 64
#define CCH 32
#define KEYSPACE (SDIM*SDIM*SDIM*SDIM)   // 16,777,216
#define NWORDS (KEYSPACE/32)             // 524,288
#define SCAN_BLOCKS 512
#define SCAN_TPB 1024                    // 512*1024 = 524,288 words
#define NMAX (1<<20)

__device__ unsigned int g_bitmap[NWORDS];
__device__ unsigned int g_dup[NWORDS];
__device__ unsigned int g_wordpfx[NWORDS];
__device__ unsigned int g_keys[NMAX];
__device__ unsigned int g_blocksums[SCAN_BLOCKS];
__device__ unsigned int g_unique;

// ----------------------------------------------- zero both bitmaps (4MB)
__global__ void zero_bitmaps_kernel() {
    int i = blockIdx.x * blockDim.x + threadIdx.x;
    if (i < NWORDS / 4) {
        ((uint4*)g_bitmap)[i] = make_uint4(0u, 0u, 0u, 0u);
        ((uint4*)g_dup)[i]    = make_uint4(0u, 0u, 0u, 0u);
    }
}

// ------------------------------------- mark presence bits + dup detection
__global__ void mark_kernel(const int4* __restrict__ coords, int n) {
    int i = blockIdx.x * blockDim.x + threadIdx.x;
    if (i >= n) return;
    int4 c = coords[i];
    unsigned int k = ((unsigned)((c.x * SDIM + c.y) * SDIM + c.z)) * SDIM + (unsigned)c.w;
    g_keys[i] = k;
    unsigned int bit = 1u << (k & 31);
    unsigned int old = atomicOr(&g_bitmap[k >> 5], bit);
    if (old & bit) atomicOr(&g_dup[k >> 5], bit);   // second+ arrival
}

// --------------------------------------------- scan pass 1: per-block sums
__global__ void scan_p1() {
    int gid = blockIdx.x * SCAN_TPB + threadIdx.x;
    int v = __popc(g_bitmap[gid]);
    __shared__ int warpsum[32];
    #pragma unroll
    for (int o = 16; o; o >>= 1) v += __shfl_down_sync(0xFFFFFFFFu, v, o);
    if ((threadIdx.x & 31) == 0) warpsum[threadIdx.x >> 5] = v;
    __syncthreads();
    if (threadIdx.x < 32) {
        int s = warpsum[threadIdx.x];
        #pragma unroll
        for (int o = 16; o; o >>= 1) s += __shfl_down_sync(0xFFFFFFFFu, s, o);
        if (threadIdx.x == 0) g_blocksums[blockIdx.x] = (unsigned)s;
    }
}

// ---------------------- scan pass 2: scan block sums, record unique total
__global__ void scan_p2() {
    __shared__ unsigned int sh[SCAN_BLOCKS];
    unsigned int v = g_blocksums[threadIdx.x];
    sh[threadIdx.x] = v;
    __syncthreads();
    for (int o = 1; o < SCAN_BLOCKS; o <<= 1) {
        unsigned int t = (threadIdx.x >= (unsigned)o) ? sh[threadIdx.x - o] : 0u;
        __syncthreads();
        sh[threadIdx.x] += t;
        __syncthreads();
    }
    if (threadIdx.x == SCAN_BLOCKS - 1) g_unique = sh[threadIdx.x];  // total
    g_blocksums[threadIdx.x] = sh[threadIdx.x] - v;                  // exclusive
}

// -------------------------- scan pass 3: per-word exclusive prefix popcount
__global__ void scan_p3() {
    __shared__ unsigned int sh[SCAN_TPB];
    int gid = blockIdx.x * SCAN_TPB + threadIdx.x;
    unsigned int v = __popc(g_bitmap[gid]);
    sh[threadIdx.x] = v;
    __syncthreads();
    for (int o = 1; o < SCAN_TPB; o <<= 1) {
        unsigned int t = (threadIdx.x >= (unsigned)o) ? sh[threadIdx.x - o] : 0u;
        __syncthreads();
        sh[threadIdx.x] += t;
        __syncthreads();
    }
    g_wordpfx[gid] = g_blocksums[blockIdx.x] + sh[threadIdx.x] - v;
}

// ---------------------------- zero the ~3% duplicate rows (atomic targets)
__global__ void dup_zero_kernel(float4* __restrict__ out) {
    int w = blockIdx.x * blockDim.x + threadIdx.x;
    if (w >= NWORDS) return;
    unsigned int d = g_dup[w];
    if (!d) return;
    unsigned int word = g_bitmap[w];
    unsigned int base = g_wordpfx[w];
    while (d) {
        int b = __ffs(d) - 1;
        d &= d - 1;
        unsigned int rank = base + __popc(word & ((1u << b) - 1u));
        float4* p = out + (size_t)rank * (CCH / 4);
        #pragma unroll
        for (int j = 0; j < CCH / 4; j++)
            __stcs(p + j, make_float4(0.f, 0.f, 0.f, 0.f));
    }
}

// ------------------------------ zero padding rows [unique, n) at the tail
__global__ void pad_zero_kernel(float4* __restrict__ out, int n) {
    int t = blockIdx.x * blockDim.x + threadIdx.x;
    if (t >= n * (CCH / 4)) return;
    unsigned int row = (unsigned)t / (CCH / 4);
    if (row >= g_unique)
        __stcs(out + t, make_float4(0.f, 0.f, 0.f, 0.f));
}

// ------------------------------------------------------- scatter features
// 8 threads per point, one float4 channel-segment each
__global__ void scatter_kernel(const float4* __restrict__ feats,
                               float* __restrict__ out, int n) {
    int t = blockIdx.x * blockDim.x + threadIdx.x;
    if (t >= n * 8) return;
    int i = t >> 3;
    int g = t & 7;
    unsigned int k = g_keys[i];
    unsigned int w = k >> 5;
    unsigned int b = k & 31;
    unsigned int word = g_bitmap[w];
    unsigned int rank = g_wordpfx[w] + __popc(word & ((1u << b) - 1u));
    bool isdup = (g_dup[w] >> b) & 1u;
    float4 f = __ldcs(feats + i * 8 + g);
    float* dst = out + (size_t)rank * CCH + g * 4;
    if (isdup) {
        atomicAdd(dst + 0, f.x);
        atomicAdd(dst + 1, f.y);
        atomicAdd(dst + 2, f.z);
        atomicAdd(dst + 3, f.w);
    } else {
        __stcs((float4*)dst, f);
    }
}

extern "C" void kernel_launch(void* const* d_in, const int* in_sizes, int n_in,
                              void* d_out, int out_size) {
    const int4*   coords = (const int4*)d_in[0];
    const float4* feats  = (const float4*)d_in[1];
    float*        out    = (float*)d_out;
    int n = in_sizes[0] / 4;

    zero_bitmaps_kernel<<<(NWORDS / 4 + 255) / 256, 256>>>();
    mark_kernel<<<(n + 255) / 256, 256>>>(coords, n);
    scan_p1<<<SCAN_BLOCKS, SCAN_TPB>>>();
    scan_p2<<<1, SCAN_BLOCKS>>>();
    scan_p3<<<SCAN_BLOCKS, SCAN_TPB>>>();
    dup_zero_kernel<<<(NWORDS + 255) / 256, 256>>>((float4*)d_out);
    pad_zero_kernel<<<(n * 8 + 255) / 256, 256>>>((float4*)d_out, n);
    scatter_kernel<<<(n * 8 + 255) / 256, 256>>>(feats, out, n);
}

// round 5
// speedup vs baseline: 1.4588x; 1.0908x over previous
#include <cuda_runtime.h>
#include <stdint.h>

#define SDIM 64
#define CCH 32
#define KEYSPACE (SDIM*SDIM*SDIM*SDIM)   // 16,777,216
#define NWORDS (KEYSPACE/32)             // 524,288
#define SCAN_TPB 1024
#define SCAN_TILES (NWORDS / SCAN_TPB)   // 512
#define NMAX (1<<20)

__device__ unsigned int g_bitmap[NWORDS];
__device__ unsigned int g_dup[NWORDS];
__device__ uint4        g_meta[NWORDS];     // {bitmap, wordpfx, dup, 0}
__device__ unsigned int g_keys[NMAX];
__device__ unsigned int g_unique;
__device__ unsigned int g_tilecounter;
__device__ volatile unsigned long long g_tilestate[SCAN_TILES]; // (flag<<32)|sum

#define FLAG_PARTIAL   1ull
#define FLAG_INCLUSIVE 2ull

// ------------------------- zero bitmaps + scan state (4MB + 4KB)
__global__ void zero_state_kernel() {
    int i = blockIdx.x * blockDim.x + threadIdx.x;
    if (i < NWORDS / 4) {
        ((uint4*)g_bitmap)[i] = make_uint4(0u, 0u, 0u, 0u);
        ((uint4*)g_dup)[i]    = make_uint4(0u, 0u, 0u, 0u);
    }
    if (i < SCAN_TILES) g_tilestate[i] = 0ull;
    if (i == 0) g_tilecounter = 0u;
}

// ------------------------------------- mark presence bits + dup detection
__global__ void mark_kernel(const int4* __restrict__ coords, int n) {
    int i = blockIdx.x * blockDim.x + threadIdx.x;
    if (i >= n) return;
    int4 c = coords[i];
    unsigned int k = ((unsigned)((c.x * SDIM + c.y) * SDIM + c.z)) * SDIM + (unsigned)c.w;
    g_keys[i] = k;
    unsigned int bit = 1u << (k & 31);
    unsigned int old = atomicOr(&g_bitmap[k >> 5], bit);
    if (old & bit) atomicOr(&g_dup[k >> 5], bit);   // second+ arrival
}

// ---------------- single-pass scan: decoupled lookback, writes packed meta
__global__ void scan_fused_kernel() {
    __shared__ unsigned int sh_warp[32];
    __shared__ unsigned int sh_tile;
    __shared__ unsigned int sh_offset;

    unsigned int tid  = threadIdx.x;
    unsigned int lane = tid & 31, wid = tid >> 5;

    if (tid == 0) sh_tile = atomicAdd(&g_tilecounter, 1u);
    __syncthreads();
    unsigned int tile = sh_tile;
    unsigned int gid  = tile * SCAN_TPB + tid;

    unsigned int w = g_bitmap[gid];
    unsigned int d = g_dup[gid];
    unsigned int v = __popc(w);

    // warp inclusive scan
    unsigned int inc = v;
    #pragma unroll
    for (int o = 1; o < 32; o <<= 1) {
        unsigned int t = __shfl_up_sync(0xFFFFFFFFu, inc, o);
        if (lane >= o) inc += t;
    }
    if (lane == 31) sh_warp[wid] = inc;
    __syncthreads();

    // warp 0 scans the 32 warp sums (exclusive), computes block total
    if (wid == 0) {
        unsigned int s = sh_warp[lane];
        unsigned int si = s;
        #pragma unroll
        for (int o = 1; o < 32; o <<= 1) {
            unsigned int t = __shfl_up_sync(0xFFFFFFFFu, si, o);
            if (lane >= o) si += t;
        }
        sh_warp[lane] = si - s;                 // exclusive warp offset
        if (lane == 31) {
            unsigned int blocktotal = si;
            if (tile == 0) {
                __threadfence();
                g_tilestate[tile] = (FLAG_INCLUSIVE << 32) | blocktotal;
                sh_offset = 0u;
                if (tile == SCAN_TILES - 1) g_unique = blocktotal;
            } else {
                // publish partial first so successors don't spin on us
                __threadfence();
                g_tilestate[tile] = (FLAG_PARTIAL << 32) | blocktotal;
                // decoupled lookback
                unsigned int offset = 0;
                int j = (int)tile - 1;
                while (j >= 0) {
                    unsigned long long st = g_tilestate[j];
                    unsigned long long flag = st >> 32;
                    if (flag == FLAG_INCLUSIVE) { offset += (unsigned int)st; break; }
                    if (flag == FLAG_PARTIAL)   { offset += (unsigned int)st; j--; continue; }
                    // flag 0: spin
                }
                __threadfence();
                g_tilestate[tile] = (FLAG_INCLUSIVE << 32) | (offset + blocktotal);
                sh_offset = offset;
                if (tile == SCAN_TILES - 1) g_unique = offset + blocktotal;
            }
        }
    }
    __syncthreads();

    unsigned int pfx = sh_offset + sh_warp[wid] + inc - v;   // exclusive
    g_meta[gid] = make_uint4(w, pfx, d, 0u);
}

// ------- zero duplicate rows (atomic targets) + padding rows [unique, n)
__global__ void dup_pad_zero_kernel(float4* __restrict__ out, int n) {
    int t = blockIdx.x * blockDim.x + threadIdx.x;
    if (t >= NWORDS) return;

    // padding part: first (n - unique)*8 threads each zero one float4
    unsigned int u = g_unique;
    unsigned int padf4 = (unsigned)(n - (int)u) * (CCH / 4);
    if ((unsigned)t < padf4)
        __stcs(out + (size_t)u * (CCH / 4) + t, make_float4(0.f, 0.f, 0.f, 0.f));

    // dup part: word t
    uint4 m = g_meta[t];
    unsigned int d = m.z;
    if (!d) return;
    unsigned int word = m.x, base = m.y;
    while (d) {
        int b = __ffs(d) - 1;
        d &= d - 1;
        unsigned int rank = base + __popc(word & ((1u << b) - 1u));
        float4* p = out + (size_t)rank * (CCH / 4);
        #pragma unroll
        for (int j = 0; j < CCH / 4; j++)
            __stcs(p + j, make_float4(0.f, 0.f, 0.f, 0.f));
    }
}

// ------------------------------------------------------- scatter features
// 8 threads per point, one float4 channel-segment each
__global__ void scatter_kernel(const float4* __restrict__ feats,
                               float* __restrict__ out, int n) {
    int t = blockIdx.x * blockDim.x + threadIdx.x;
    if (t >= n * 8) return;
    int i = t >> 3;
    int g = t & 7;
    unsigned int k = g_keys[i];
    unsigned int w = k >> 5;
    unsigned int b = k & 31;
    uint4 m = __ldg(&g_meta[w]);               // {bitmap, pfx, dup, 0}
    unsigned int rank = m.y + __popc(m.x & ((1u << b) - 1u));
    bool isdup = (m.z >> b) & 1u;
    float4 f = __ldcs(feats + i * 8 + g);
    float* dst = out + (size_t)rank * CCH + g * 4;
    if (isdup) {
        atomicAdd(dst + 0, f.x);
        atomicAdd(dst + 1, f.y);
        atomicAdd(dst + 2, f.z);
        atomicAdd(dst + 3, f.w);
    } else {
        __stcs((float4*)dst, f);
    }
}

extern "C" void kernel_launch(void* const* d_in, const int* in_sizes, int n_in,
                              void* d_out, int out_size) {
    const int4*   coords = (const int4*)d_in[0];
    const float4* feats  = (const float4*)d_in[1];
    float*        out    = (float*)d_out;
    int n = in_sizes[0] / 4;

    zero_state_kernel<<<(NWORDS / 4 + 255) / 256, 256>>>();
    mark_kernel<<<(n + 255) / 256, 256>>>(coords, n);
    scan_fused_kernel<<<SCAN_TILES, SCAN_TPB>>>();
    dup_pad_zero_kernel<<<(NWORDS + 255) / 256, 256>>>((float4*)d_out, n);
    scatter_kernel<<<(n * 8 + 255) / 256, 256>>>(feats, out, n);
}